// round 4
// baseline (speedup 1.0000x reference)
#include <cuda_runtime.h>
#include <cuda_bf16.h>
#include <math.h>
#include <stdint.h>

// ---------------- problem constants ----------------
#define BB 4
#define TT 1024
#define DD 1024
#define HH 16
#define HD 64
#define LL 8
#define VV 4096
#define BT (BB*TT)       // 4096
#define D4 (4*DD)        // 4096

typedef __nv_bfloat16 bf16;

// ---------------- scratch (no alloc allowed) ----------------
__device__ float g_x[BT*DD];
// activations, bf16 hi/lo
__device__ bf16 g_hh[BT*DD], g_hl[BT*DD];
__device__ bf16 g_qh[BT*DD], g_ql[BT*DD];
__device__ bf16 g_kh[BT*DD], g_kl[BT*DD];
__device__ bf16 g_vh[BT*DD], g_vl[BT*DD];
__device__ bf16 g_yh[BT*DD], g_yl[BT*DD];
__device__ bf16 g_mh[(size_t)BT*D4], g_ml[(size_t)BT*D4];
// weights, bf16 hi/lo
__device__ bf16 g_wqh[LL*DD*DD], g_wql[LL*DD*DD];
__device__ bf16 g_wkh[LL*DD*DD], g_wkl[LL*DD*DD];
__device__ bf16 g_wvh[LL*DD*DD], g_wvl[LL*DD*DD];
__device__ bf16 g_wph[LL*DD*DD], g_wpl[LL*DD*DD];
__device__ bf16 g_w1h[(size_t)LL*D4*DD], g_w1l[(size_t)LL*D4*DD];
__device__ bf16 g_w2h[(size_t)LL*D4*DD], g_w2l[(size_t)LL*D4*DD];
__device__ bf16 g_wlh[VV*DD], g_wll[VV*DD];
__device__ bf16 g_wdh[VV*DD], g_wdl[VV*DD];

// ---------------- helpers ----------------
__device__ __forceinline__ float warpSum(float v) {
    #pragma unroll
    for (int o = 16; o > 0; o >>= 1) v += __shfl_xor_sync(0xffffffffu, v, o);
    return v;
}

__device__ __forceinline__ uint32_t pack2bf(float a, float b) {
    __nv_bfloat162 h = __floats2bfloat162_rn(a, b);
    return *reinterpret_cast<uint32_t*>(&h);
}

__device__ __forceinline__ void split2(float f, float& hi, float& lo) {
    hi = __bfloat162float(__float2bfloat16_rn(f));
    lo = f - hi;
}

#define MMA_BF16(c, a, b0v, b1v) \
  asm volatile("mma.sync.aligned.m16n8k16.row.col.f32.bf16.bf16.f32 " \
    "{%0,%1,%2,%3}, {%4,%5,%6,%7}, {%8,%9}, {%0,%1,%2,%3};" \
    : "+f"((c)[0]), "+f"((c)[1]), "+f"((c)[2]), "+f"((c)[3]) \
    : "r"((a)[0]), "r"((a)[1]), "r"((a)[2]), "r"((a)[3]), "r"(b0v), "r"(b1v))

__device__ __forceinline__ void ldsm4(uint32_t* r, const uint32_t* p) {
    uint32_t a = (uint32_t)__cvta_generic_to_shared(p);
    asm volatile("ldmatrix.sync.aligned.m8n8.x4.shared.b16 {%0,%1,%2,%3}, [%4];"
        : "=r"(r[0]), "=r"(r[1]), "=r"(r[2]), "=r"(r[3]) : "r"(a));
}
__device__ __forceinline__ void ldsm4t(uint32_t* r, const uint32_t* p) {
    uint32_t a = (uint32_t)__cvta_generic_to_shared(p);
    asm volatile("ldmatrix.sync.aligned.m8n8.x4.trans.shared.b16 {%0,%1,%2,%3}, [%4];"
        : "=r"(r[0]), "=r"(r[1]), "=r"(r[2]), "=r"(r[3]) : "r"(a));
}

__device__ __forceinline__ void cpa(uint32_t* dst, const void* src) {
    uint32_t d = (uint32_t)__cvta_generic_to_shared(dst);
    asm volatile("cp.async.cg.shared.global [%0], [%1], 16;" :: "r"(d), "l"(src));
}
#define CP_COMMIT asm volatile("cp.async.commit_group;")

// ---------------- weight conversion: fp32 -> bf16 hi/lo ----------------
__global__ void cvt_kernel(const float* __restrict__ s, bf16* __restrict__ dh,
                           bf16* __restrict__ dl, int n4) {
    int i = blockIdx.x * blockDim.x + threadIdx.x;
    if (i >= n4) return;
    float4 v = reinterpret_cast<const float4*>(s)[i];
    float h0,l0,h1,l1,h2,l2,h3,l3;
    split2(v.x,h0,l0); split2(v.y,h1,l1); split2(v.z,h2,l2); split2(v.w,h3,l3);
    reinterpret_cast<uint32_t*>(dh)[i*2]   = pack2bf(h0,h1);
    reinterpret_cast<uint32_t*>(dh)[i*2+1] = pack2bf(h2,h3);
    reinterpret_cast<uint32_t*>(dl)[i*2]   = pack2bf(l0,l1);
    reinterpret_cast<uint32_t*>(dl)[i*2+1] = pack2bf(l2,l3);
}

// ---------------- embedding ----------------
__global__ void embed_kernel(const int* __restrict__ idx,
                             const float* __restrict__ tok,
                             const float* __restrict__ pos,
                             float* __restrict__ x) {
    int row = blockIdx.x;
    int t   = row & (TT - 1);
    int token = idx[row];
    const float4* tr = reinterpret_cast<const float4*>(tok + (size_t)token * DD);
    const float4* pr = reinterpret_cast<const float4*>(pos + (size_t)t * DD);
    float4* xr = reinterpret_cast<float4*>(x + (size_t)row * DD);
    int i = threadIdx.x;
    float4 a = tr[i], p = pr[i];
    float4 o; o.x = a.x + p.x; o.y = a.y + p.y; o.z = a.z + p.z; o.w = a.w + p.w;
    xr[i] = o;
}

// ---------------- layernorm -> bf16 hi/lo ----------------
__global__ void ln_kernel(const float* __restrict__ in, bf16* __restrict__ outh,
                          bf16* __restrict__ outl,
                          const float* __restrict__ w, const float* __restrict__ b) {
    __shared__ float red[8];
    __shared__ float s_mean, s_rstd;
    int row = blockIdx.x;
    int tid = threadIdx.x;
    int lane = tid & 31, wid = tid >> 5;

    const float4* r = reinterpret_cast<const float4*>(in + (size_t)row * DD);
    float4 v = r[tid];

    float s = v.x + v.y + v.z + v.w;
    s = warpSum(s);
    if (lane == 0) red[wid] = s;
    __syncthreads();
    if (wid == 0) {
        float t = (lane < 8) ? red[lane] : 0.f;
        t = warpSum(t);
        if (lane == 0) s_mean = t * (1.0f / DD);
    }
    __syncthreads();
    float mean = s_mean;
    float dx = v.x - mean, dy = v.y - mean, dz = v.z - mean, dw = v.w - mean;
    float sq = dx*dx + dy*dy + dz*dz + dw*dw;
    sq = warpSum(sq);
    __syncthreads();
    if (lane == 0) red[wid] = sq;
    __syncthreads();
    if (wid == 0) {
        float t = (lane < 8) ? red[lane] : 0.f;
        t = warpSum(t);
        if (lane == 0) s_rstd = rsqrtf(t * (1.0f / DD) + 1e-5f);
    }
    __syncthreads();
    float rstd = s_rstd;

    const float4* wr = reinterpret_cast<const float4*>(w);
    const float4* br = reinterpret_cast<const float4*>(b);
    float4 ww = wr[tid], bb = br[tid];
    float ox = dx * rstd * ww.x + bb.x;
    float oy = dy * rstd * ww.y + bb.y;
    float oz = dz * rstd * ww.z + bb.z;
    float ow = dw * rstd * ww.w + bb.w;
    float h0,l0,h1,l1,h2,l2,h3,l3;
    split2(ox,h0,l0); split2(oy,h1,l1); split2(oz,h2,l2); split2(ow,h3,l3);
    uint32_t* oh = reinterpret_cast<uint32_t*>(outh) + (size_t)row * 512;
    uint32_t* ol = reinterpret_cast<uint32_t*>(outl) + (size_t)row * 512;
    oh[tid*2]   = pack2bf(h0,h1);
    oh[tid*2+1] = pack2bf(h2,h3);
    ol[tid*2]   = pack2bf(l0,l1);
    ol[tid*2+1] = pack2bf(l2,l3);
}

// ---------------- bf16-split tensor-core GEMM, cp.async pipelined ----------------
// C[M,N] = (Ah+Al)[M,K] * (Wh+Wl)[N,K]^T  (3-term split)
// 256x128 tile, BK=32, 512 threads (16 warps 8x2), warp tile 32x64.
// stage layout (u32): Ah[256][20] | Al | Bh[128][20] | Bl  = 15360 u32/stage
__device__ __forceinline__ void gemm_issue(uint32_t* st,
        const bf16* __restrict__ Ah, const bf16* __restrict__ Al,
        const bf16* __restrict__ Wh, const bf16* __restrict__ Wl,
        size_t ko, int bm, int bn, int K, int arow, int ac, int brow, int bc) {
    #pragma unroll
    for (int i = 0; i < 2; i++) {
        int c = ac + i;
        cpa(st + arow*20 + c*4,        Ah + (size_t)(bm+arow)*K + ko + c*8);
        cpa(st + 5120 + arow*20 + c*4, Al + (size_t)(bm+arow)*K + ko + c*8);
    }
    cpa(st + 10240 + brow*20 + bc*4, Wh + (size_t)(bn+brow)*K + ko + bc*8);
    cpa(st + 12800 + brow*20 + bc*4, Wl + (size_t)(bn+brow)*K + ko + bc*8);
}

template <int GELU, int RES, int OUTBF>
__global__ void __launch_bounds__(512, 1)
mma_gemm(const bf16* __restrict__ Ah, const bf16* __restrict__ Al,
         const bf16* __restrict__ Wh, const bf16* __restrict__ Wl,
         const float* __restrict__ bias, const float* __restrict__ res,
         float* __restrict__ C, bf16* __restrict__ Ch, bf16* __restrict__ Cl,
         int M, int N, int K) {
    extern __shared__ uint32_t sm[];

    const int t = threadIdx.x;
    const int lane = t & 31, wid = t >> 5;
    const int wm = (wid & 7) * 32;
    const int wn = (wid >> 3) * 64;
    const int gid = lane >> 2, tig = lane & 3;
    const int bm = blockIdx.y * 256;
    const int bn = blockIdx.x * 128;

    float acc[2][8][4];
    #pragma unroll
    for (int mt = 0; mt < 2; mt++)
        #pragma unroll
        for (int nt = 0; nt < 8; nt++)
            #pragma unroll
            for (int i = 0; i < 4; i++) acc[mt][nt][i] = 0.f;

    // cp.async indices
    const int arow = t >> 1, ac = (t & 1) * 2;
    const int brow = t >> 2, bc = t & 3;
    // ldmatrix bases
    const int a_r = wm + (lane & 15);
    const int a_cofs = (lane >> 4) << 2;
    const int b_r = wn + (lane & 7) + ((lane & 16) ? 8 : 0);
    const int b_cofs = (lane & 8) ? 4 : 0;

    const int ktot = K >> 5;
    gemm_issue(sm, Ah, Al, Wh, Wl, 0, bm, bn, K, arow, ac, brow, bc);
    CP_COMMIT;

    for (int kt = 0; kt < ktot; kt++) {
        if (kt + 1 < ktot) {
            gemm_issue(sm + ((kt+1)&1)*15360, Ah, Al, Wh, Wl,
                       (size_t)(kt+1)*32, bm, bn, K, arow, ac, brow, bc);
            CP_COMMIT;
            asm volatile("cp.async.wait_group 1;");
        } else {
            asm volatile("cp.async.wait_group 0;");
        }
        __syncthreads();
        uint32_t* st = sm + (kt & 1) * 15360;

        #pragma unroll
        for (int ks = 0; ks < 2; ks++) {
            uint32_t ah[2][4], al[2][4];
            int acol = ks * 8 + a_cofs;
            ldsm4(ah[0], st + (size_t)a_r * 20 + acol);
            ldsm4(ah[1], st + (size_t)(a_r + 16) * 20 + acol);
            ldsm4(al[0], st + 5120 + (size_t)a_r * 20 + acol);
            ldsm4(al[1], st + 5120 + (size_t)(a_r + 16) * 20 + acol);
            #pragma unroll
            for (int ntp = 0; ntp < 4; ntp++) {
                int br2 = b_r + ntp * 16;
                int bcol = ks * 8 + b_cofs;
                uint32_t bh[4], bl[4];
                ldsm4(bh, st + 10240 + (size_t)br2 * 20 + bcol);
                ldsm4(bl, st + 12800 + (size_t)br2 * 20 + bcol);
                #pragma unroll
                for (int half = 0; half < 2; half++) {
                    int nt = ntp * 2 + half;
                    #pragma unroll
                    for (int mt = 0; mt < 2; mt++) {
                        MMA_BF16(acc[mt][nt], ah[mt], bh[half*2], bh[half*2+1]);
                        MMA_BF16(acc[mt][nt], ah[mt], bl[half*2], bl[half*2+1]);
                        MMA_BF16(acc[mt][nt], al[mt], bh[half*2], bh[half*2+1]);
                    }
                }
            }
        }
        __syncthreads();
    }

    // epilogue
    #pragma unroll
    for (int mt = 0; mt < 2; mt++) {
        int r0 = bm + wm + mt * 16 + gid;
        #pragma unroll
        for (int nt = 0; nt < 8; nt++) {
            int c = bn + wn + nt * 8 + tig * 2;
            float b0 = 0.f, b1 = 0.f;
            if (bias) { b0 = bias[c]; b1 = bias[c + 1]; }
            float v0 = acc[mt][nt][0] + b0, v1 = acc[mt][nt][1] + b1;
            float v2 = acc[mt][nt][2] + b0, v3 = acc[mt][nt][3] + b1;
            if (RES) {
                float2 ra = *reinterpret_cast<const float2*>(&res[(size_t)r0 * N + c]);
                float2 rb = *reinterpret_cast<const float2*>(&res[(size_t)(r0 + 8) * N + c]);
                v0 += ra.x; v1 += ra.y; v2 += rb.x; v3 += rb.y;
            }
            if (GELU) {
                v0 = 0.5f * v0 * (1.0f + erff(v0 * 0.70710678118654752f));
                v1 = 0.5f * v1 * (1.0f + erff(v1 * 0.70710678118654752f));
                v2 = 0.5f * v2 * (1.0f + erff(v2 * 0.70710678118654752f));
                v3 = 0.5f * v3 * (1.0f + erff(v3 * 0.70710678118654752f));
            }
            if (OUTBF) {
                float h0,l0,h1,l1;
                split2(v0,h0,l0); split2(v1,h1,l1);
                *reinterpret_cast<uint32_t*>(Ch + (size_t)r0 * N + c) = pack2bf(h0,h1);
                *reinterpret_cast<uint32_t*>(Cl + (size_t)r0 * N + c) = pack2bf(l0,l1);
                split2(v2,h0,l0); split2(v3,h1,l1);
                *reinterpret_cast<uint32_t*>(Ch + (size_t)(r0+8) * N + c) = pack2bf(h0,h1);
                *reinterpret_cast<uint32_t*>(Cl + (size_t)(r0+8) * N + c) = pack2bf(l0,l1);
            } else {
                *reinterpret_cast<float2*>(&C[(size_t)r0 * N + c])       = make_float2(v0, v1);
                *reinterpret_cast<float2*>(&C[(size_t)(r0 + 8) * N + c]) = make_float2(v2, v3);
            }
        }
    }
}

// ---------------- tensorized flash attention (bf16 hi/lo inputs) ----------------
// block: 64 q x (h,b), 128 threads (4 warps x 16q). K/V tiles of 32.
__global__ void __launch_bounds__(128)
attn_kernel(const bf16* __restrict__ gqh, const bf16* __restrict__ gql,
            const bf16* __restrict__ gkh, const bf16* __restrict__ gkl,
            const bf16* __restrict__ gvh, const bf16* __restrict__ gvl,
            bf16* __restrict__ gyh, bf16* __restrict__ gyl) {
    __shared__ uint32_t Qh[64*36], Ql[64*36];
    __shared__ uint32_t Kh[32*36], Kl[32*36];
    __shared__ uint32_t Vh[32*36], Vl[32*36];

    const int q0 = blockIdx.x * 64;
    const int h  = blockIdx.y;
    const int b  = blockIdx.z;
    const int tid = threadIdx.x;
    const int lane = tid & 31, wid = tid >> 5;
    const int gid = lane >> 2, tig = lane & 3;
    const int wq = wid * 16;
    const size_t base = ((size_t)b * TT) * DD + h * HD;

    // stage Q tile (64 x 64 bf16, hi+lo)
    #pragma unroll
    for (int i = 0; i < 4; i++) {
        int chunk = tid + i * 128;
        int row = chunk >> 3, c = chunk & 7;
        const size_t g = base + (size_t)(q0 + row) * DD + c * 8;
        *reinterpret_cast<uint4*>(Qh + row*36 + c*4) = *reinterpret_cast<const uint4*>(gqh + g);
        *reinterpret_cast<uint4*>(Ql + row*36 + c*4) = *reinterpret_cast<const uint4*>(gql + g);
    }

    float m0 = -1e30f, m1 = -1e30f, l0s = 0.f, l1s = 0.f;
    float acc[8][4];
    #pragma unroll
    for (int i = 0; i < 8; i++)
        #pragma unroll
        for (int j = 0; j < 4; j++) acc[i][j] = 0.f;

    const int qg0 = q0 + wq + gid;
    const int qmax = q0 + wq + 15;
    const int ntiles = (q0 + 64) >> 5;

    const int a_r = wq + (lane & 15);
    const int a_cofs = (lane >> 4) << 2;
    const int b_r = (lane & 7) + ((lane & 16) ? 8 : 0);
    const int b_cofs = (lane & 8) ? 4 : 0;
    const int v_r = (lane & 7) + ((lane & 8) ? 8 : 0);
    const int v_cofs = (lane & 16) ? 4 : 0;

    for (int kt = 0; kt < ntiles; kt++) {
        int k0 = kt * 32;
        __syncthreads();
        #pragma unroll
        for (int i = 0; i < 2; i++) {
            int chunk = tid + i * 128;
            int row = chunk >> 3, c = chunk & 7;
            const size_t g = base + (size_t)(k0 + row) * DD + c * 8;
            *reinterpret_cast<uint4*>(Kh + row*36 + c*4) = *reinterpret_cast<const uint4*>(gkh + g);
            *reinterpret_cast<uint4*>(Kl + row*36 + c*4) = *reinterpret_cast<const uint4*>(gkl + g);
            *reinterpret_cast<uint4*>(Vh + row*36 + c*4) = *reinterpret_cast<const uint4*>(gvh + g);
            *reinterpret_cast<uint4*>(Vl + row*36 + c*4) = *reinterpret_cast<const uint4*>(gvl + g);
        }
        __syncthreads();
        if (k0 > qmax) continue;

        // ---- scores ----
        float s[4][4];
        #pragma unroll
        for (int nt = 0; nt < 4; nt++)
            #pragma unroll
            for (int j = 0; j < 4; j++) s[nt][j] = 0.f;

        #pragma unroll
        for (int ks = 0; ks < 4; ks++) {
            uint32_t ah[4], al[4];
            int acol = ks * 8 + a_cofs;
            ldsm4(ah, Qh + (size_t)a_r * 36 + acol);
            ldsm4(al, Ql + (size_t)a_r * 36 + acol);
            #pragma unroll
            for (int ntp = 0; ntp < 2; ntp++) {
                int brow = b_r + ntp * 16;
                int bcol = ks * 8 + b_cofs;
                uint32_t bh[4], bl[4];
                ldsm4(bh, Kh + (size_t)brow * 36 + bcol);
                ldsm4(bl, Kl + (size_t)brow * 36 + bcol);
                #pragma unroll
                for (int half = 0; half < 2; half++) {
                    int nt = ntp * 2 + half;
                    MMA_BF16(s[nt], ah, bh[half*2], bh[half*2+1]);
                    MMA_BF16(s[nt], ah, bl[half*2], bl[half*2+1]);
                    MMA_BF16(s[nt], al, bh[half*2], bh[half*2+1]);
                }
            }
        }

        // scale + causal mask
        #pragma unroll
        for (int nt = 0; nt < 4; nt++)
            #pragma unroll
            for (int j = 0; j < 4; j++) s[nt][j] *= 0.125f;
        if (k0 + 31 > q0 + wq) {
            #pragma unroll
            for (int nt = 0; nt < 4; nt++) {
                int kg = k0 + nt * 8 + tig * 2;
                if (kg     > qg0)     s[nt][0] = -1e30f;
                if (kg + 1 > qg0)     s[nt][1] = -1e30f;
                if (kg     > qg0 + 8) s[nt][2] = -1e30f;
                if (kg + 1 > qg0 + 8) s[nt][3] = -1e30f;
            }
        }

        // online softmax
        float mx0 = -1e30f, mx1 = -1e30f;
        #pragma unroll
        for (int nt = 0; nt < 4; nt++) {
            mx0 = fmaxf(mx0, fmaxf(s[nt][0], s[nt][1]));
            mx1 = fmaxf(mx1, fmaxf(s[nt][2], s[nt][3]));
        }
        mx0 = fmaxf(mx0, __shfl_xor_sync(0xffffffffu, mx0, 1));
        mx0 = fmaxf(mx0, __shfl_xor_sync(0xffffffffu, mx0, 2));
        mx1 = fmaxf(mx1, __shfl_xor_sync(0xffffffffu, mx1, 1));
        mx1 = fmaxf(mx1, __shfl_xor_sync(0xffffffffu, mx1, 2));
        float mn0 = fmaxf(m0, mx0), mn1 = fmaxf(m1, mx1);
        float sc0 = __expf(m0 - mn0), sc1 = __expf(m1 - mn1);
        m0 = mn0; m1 = mn1;
        float rs0 = 0.f, rs1 = 0.f;
        #pragma unroll
        for (int nt = 0; nt < 4; nt++) {
            s[nt][0] = __expf(s[nt][0] - mn0);
            s[nt][1] = __expf(s[nt][1] - mn0);
            s[nt][2] = __expf(s[nt][2] - mn1);
            s[nt][3] = __expf(s[nt][3] - mn1);
            rs0 += s[nt][0] + s[nt][1];
            rs1 += s[nt][2] + s[nt][3];
        }
        rs0 += __shfl_xor_sync(0xffffffffu, rs0, 1);
        rs0 += __shfl_xor_sync(0xffffffffu, rs0, 2);
        rs1 += __shfl_xor_sync(0xffffffffu, rs1, 1);
        rs1 += __shfl_xor_sync(0xffffffffu, rs1, 2);
        l0s = l0s * sc0 + rs0;
        l1s = l1s * sc1 + rs1;
        #pragma unroll
        for (int ntd = 0; ntd < 8; ntd++) {
            acc[ntd][0] *= sc0; acc[ntd][1] *= sc0;
            acc[ntd][2] *= sc1; acc[ntd][3] *= sc1;
        }

        // ---- PV ----
        #pragma unroll
        for (int ks2 = 0; ks2 < 2; ks2++) {
            int e = ks2 * 2, o = e + 1;
            uint32_t ph[4], pl[4];
            {
                float h0,L0,h1,L1;
                split2(s[e][0],h0,L0); split2(s[e][1],h1,L1);
                ph[0] = pack2bf(h0,h1); pl[0] = pack2bf(L0,L1);
                split2(s[e][2],h0,L0); split2(s[e][3],h1,L1);
                ph[1] = pack2bf(h0,h1); pl[1] = pack2bf(L0,L1);
                split2(s[o][0],h0,L0); split2(s[o][1],h1,L1);
                ph[2] = pack2bf(h0,h1); pl[2] = pack2bf(L0,L1);
                split2(s[o][2],h0,L0); split2(s[o][3],h1,L1);
                ph[3] = pack2bf(h0,h1); pl[3] = pack2bf(L0,L1);
            }
            #pragma unroll
            for (int ntp = 0; ntp < 4; ntp++) {
                int vrow = ks2 * 16 + v_r;
                int vcol = ntp * 8 + v_cofs;
                uint32_t bh[4], bl[4];
                ldsm4t(bh, Vh + (size_t)vrow * 36 + vcol);
                ldsm4t(bl, Vl + (size_t)vrow * 36 + vcol);
                #pragma unroll
                for (int half = 0; half < 2; half++) {
                    int ntd = ntp * 2 + half;
                    MMA_BF16(acc[ntd], ph, bh[half*2], bh[half*2+1]);
                    MMA_BF16(acc[ntd], ph, bl[half*2], bl[half*2+1]);
                    MMA_BF16(acc[ntd], pl, bh[half*2], bh[half*2+1]);
                }
            }
        }
    }

    // write out (bf16 hi/lo)
    float inv0 = 1.0f / l0s, inv1 = 1.0f / l1s;
    #pragma unroll
    for (int ntd = 0; ntd < 8; ntd++) {
        int d = ntd * 8 + tig * 2;
        float h0,L0,h1,L1;
        split2(acc[ntd][0] * inv0, h0, L0); split2(acc[ntd][1] * inv0, h1, L1);
        *reinterpret_cast<uint32_t*>(gyh + base + (size_t)qg0 * DD + d) = pack2bf(h0,h1);
        *reinterpret_cast<uint32_t*>(gyl + base + (size_t)qg0 * DD + d) = pack2bf(L0,L1);
        split2(acc[ntd][2] * inv1, h0, L0); split2(acc[ntd][3] * inv1, h1, L1);
        *reinterpret_cast<uint32_t*>(gyh + base + (size_t)(qg0 + 8) * DD + d) = pack2bf(h0,h1);
        *reinterpret_cast<uint32_t*>(gyl + base + (size_t)(qg0 + 8) * DD + d) = pack2bf(L0,L1);
    }
}

// ---------------- launch ----------------
extern "C" void kernel_launch(void* const* d_in, const int* in_sizes, int n_in,
                              void* d_out, int out_size) {
    const int*   idx    = (const int*)  d_in[0];
    const float* tok    = (const float*)d_in[1];
    const float* pos    = (const float*)d_in[2];
    const float* ln1_w  = (const float*)d_in[3];
    const float* ln1_b  = (const float*)d_in[4];
    const float* Wq     = (const float*)d_in[5];
    const float* bq     = (const float*)d_in[6];
    const float* Wk     = (const float*)d_in[7];
    const float* bk     = (const float*)d_in[8];
    const float* Wv     = (const float*)d_in[9];
    const float* bv     = (const float*)d_in[10];
    const float* Wproj  = (const float*)d_in[11];
    const float* bproj  = (const float*)d_in[12];
    const float* ln2_w  = (const float*)d_in[13];
    const float* ln2_b  = (const float*)d_in[14];
    const float* W1     = (const float*)d_in[15];
    const float* b1     = (const float*)d_in[16];
    const float* W2     = (const float*)d_in[17];
    const float* b2     = (const float*)d_in[18];
    const float* lnf_w  = (const float*)d_in[19];
    const float* lnf_b  = (const float*)d_in[20];
    const float* Wlogit = (const float*)d_in[21];
    const float* Wdev   = (const float*)d_in[22];
    float* out = (float*)d_out;

    float *x;
    bf16 *hh,*hl,*qh,*ql,*kh,*kl,*vh,*vl,*yh,*yl,*mh,*ml;
    bf16 *wqh,*wql,*wkh,*wkl,*wvh,*wvl,*wph,*wpl,*w1h,*w1l,*w2h,*w2l,*wlh,*wll,*wdh,*wdl;
    cudaGetSymbolAddress((void**)&x,   g_x);
    cudaGetSymbolAddress((void**)&hh,  g_hh);  cudaGetSymbolAddress((void**)&hl,  g_hl);
    cudaGetSymbolAddress((void**)&qh,  g_qh);  cudaGetSymbolAddress((void**)&ql,  g_ql);
    cudaGetSymbolAddress((void**)&kh,  g_kh);  cudaGetSymbolAddress((void**)&kl,  g_kl);
    cudaGetSymbolAddress((void**)&vh,  g_vh);  cudaGetSymbolAddress((void**)&vl,  g_vl);
    cudaGetSymbolAddress((void**)&yh,  g_yh);  cudaGetSymbolAddress((void**)&yl,  g_yl);
    cudaGetSymbolAddress((void**)&mh,  g_mh);  cudaGetSymbolAddress((void**)&ml,  g_ml);
    cudaGetSymbolAddress((void**)&wqh, g_wqh); cudaGetSymbolAddress((void**)&wql, g_wql);
    cudaGetSymbolAddress((void**)&wkh, g_wkh); cudaGetSymbolAddress((void**)&wkl, g_wkl);
    cudaGetSymbolAddress((void**)&wvh, g_wvh); cudaGetSymbolAddress((void**)&wvl, g_wvl);
    cudaGetSymbolAddress((void**)&wph, g_wph); cudaGetSymbolAddress((void**)&wpl, g_wpl);
    cudaGetSymbolAddress((void**)&w1h, g_w1h); cudaGetSymbolAddress((void**)&w1l, g_w1l);
    cudaGetSymbolAddress((void**)&w2h, g_w2h); cudaGetSymbolAddress((void**)&w2l, g_w2l);
    cudaGetSymbolAddress((void**)&wlh, g_wlh); cudaGetSymbolAddress((void**)&wll, g_wll);
    cudaGetSymbolAddress((void**)&wdh, g_wdh); cudaGetSymbolAddress((void**)&wdl, g_wdl);

    const int SMEM = 2 * 15360 * 4;   // 122880
    cudaFuncSetAttribute(mma_gemm<0,0,1>, cudaFuncAttributeMaxDynamicSharedMemorySize, SMEM);
    cudaFuncSetAttribute(mma_gemm<0,1,0>, cudaFuncAttributeMaxDynamicSharedMemorySize, SMEM);
    cudaFuncSetAttribute(mma_gemm<1,0,1>, cudaFuncAttributeMaxDynamicSharedMemorySize, SMEM);
    cudaFuncSetAttribute(mma_gemm<0,0,0>, cudaFuncAttributeMaxDynamicSharedMemorySize, SMEM);

    // weight conversion (per launch; ~170us)
    {
        int n4q = LL*DD*DD/4;        // 2M
        int n41 = LL*D4*DD/4;        // 8M
        int n4v = VV*DD/4;           // 1M
        cvt_kernel<<<(n4q+255)/256, 256>>>(Wq,     wqh, wql, n4q);
        cvt_kernel<<<(n4q+255)/256, 256>>>(Wk,     wkh, wkl, n4q);
        cvt_kernel<<<(n4q+255)/256, 256>>>(Wv,     wvh, wvl, n4q);
        cvt_kernel<<<(n4q+255)/256, 256>>>(Wproj,  wph, wpl, n4q);
        cvt_kernel<<<(n41+255)/256, 256>>>(W1,     w1h, w1l, n41);
        cvt_kernel<<<(n41+255)/256, 256>>>(W2,     w2h, w2l, n41);
        cvt_kernel<<<(n4v+255)/256, 256>>>(Wlogit, wlh, wll, n4v);
        cvt_kernel<<<(n4v+255)/256, 256>>>(Wdev,   wdh, wdl, n4v);
    }

    embed_kernel<<<BT, 256>>>(idx, tok, pos, x);

    dim3 gD(DD / 128, BT / 256);    // N=1024 -> (8,16) = 128 CTAs
    dim3 g4(D4 / 128, BT / 256);    // N=4096 -> (32,16)
    dim3 gV(VV / 128, BT / 256);
    dim3 ga(TT / 64, HH, BB);

    for (int l = 0; l < LL; l++) {
        size_t wo = (size_t)l * DD * DD;
        size_t w4 = (size_t)l * D4 * DD;

        ln_kernel<<<BT, 256>>>(x, hh, hl, ln1_w + l * DD, ln1_b + l * DD);

        mma_gemm<0,0,1><<<gD, 512, SMEM>>>(hh, hl, wqh + wo, wql + wo, bq + l * DD,
                                           nullptr, nullptr, qh, ql, BT, DD, DD);
        mma_gemm<0,0,1><<<gD, 512, SMEM>>>(hh, hl, wkh + wo, wkl + wo, bk + l * DD,
                                           nullptr, nullptr, kh, kl, BT, DD, DD);
        mma_gemm<0,0,1><<<gD, 512, SMEM>>>(hh, hl, wvh + wo, wvl + wo, bv + l * DD,
                                           nullptr, nullptr, vh, vl, BT, DD, DD);

        attn_kernel<<<ga, 128>>>(qh, ql, kh, kl, vh, vl, yh, yl);

        mma_gemm<0,1,0><<<gD, 512, SMEM>>>(yh, yl, wph + wo, wpl + wo, bproj + l * DD,
                                           x, x, nullptr, nullptr, BT, DD, DD);

        ln_kernel<<<BT, 256>>>(x, hh, hl, ln2_w + l * DD, ln2_b + l * DD);

        mma_gemm<1,0,1><<<g4, 512, SMEM>>>(hh, hl, w1h + w4, w1l + w4, b1 + (size_t)l * D4,
                                           nullptr, nullptr, mh, ml, BT, D4, DD);
        mma_gemm<0,1,0><<<gD, 512, SMEM>>>(mh, ml, w2h + w4, w2l + w4, b2 + l * DD,
                                           x, x, nullptr, nullptr, BT, DD, D4);
    }

    ln_kernel<<<BT, 256>>>(x, hh, hl, lnf_w, lnf_b);

    mma_gemm<0,0,0><<<gV, 512, SMEM>>>(hh, hl, wlh, wll, nullptr, nullptr,
                                       out, nullptr, nullptr, BT, VV, DD);
    mma_gemm<0,0,0><<<gV, 512, SMEM>>>(hh, hl, wdh, wdl, nullptr, nullptr,
                                       out + (size_t)BT * VV, nullptr, nullptr, BT, VV, DD);
}

// round 6
// speedup vs baseline: 1.0641x; 1.0641x over previous
#include <cuda_runtime.h>
#include <cuda_bf16.h>
#include <math.h>
#include <stdint.h>

// ---------------- problem constants ----------------
#define BB 4
#define TT 1024
#define DD 1024
#define HH 16
#define HD 64
#define LL 8
#define VV 4096
#define BT (BB*TT)       // 4096
#define D4 (4*DD)        // 4096
#define D3 (3*DD)        // 3072

typedef __nv_bfloat16 bf16;

// ---------------- scratch (no alloc allowed) ----------------
__device__ float g_x[BT*DD];
__device__ bf16 g_hh[BT*DD], g_hl[BT*DD];
__device__ bf16 g_qkvh[(size_t)BT*D3], g_qkvl[(size_t)BT*D3];
__device__ bf16 g_yh[BT*DD], g_yl[BT*DD];
__device__ bf16 g_mh[(size_t)BT*D4], g_ml[(size_t)BT*D4];
// weights (preconverted hi/lo)
__device__ bf16 g_wqkvh[(size_t)LL*D3*DD], g_wqkvl[(size_t)LL*D3*DD];
__device__ bf16 g_wph[LL*DD*DD], g_wpl[LL*DD*DD];
__device__ bf16 g_w1h[(size_t)LL*D4*DD], g_w1l[(size_t)LL*D4*DD];
__device__ bf16 g_w2h[(size_t)LL*D4*DD], g_w2l[(size_t)LL*D4*DD];
__device__ bf16 g_whh[(size_t)2*VV*DD], g_whl[(size_t)2*VV*DD];
__device__ float g_bqkv[LL*D3];

// ---------------- helpers ----------------
__device__ __forceinline__ float warpSum(float v) {
    #pragma unroll
    for (int o = 16; o > 0; o >>= 1) v += __shfl_xor_sync(0xffffffffu, v, o);
    return v;
}
__device__ __forceinline__ uint32_t pack2bf(float a, float b) {
    __nv_bfloat162 h = __floats2bfloat162_rn(a, b);
    return *reinterpret_cast<uint32_t*>(&h);
}
__device__ __forceinline__ void split2(float f, float& hi, float& lo) {
    hi = __bfloat162float(__float2bfloat16_rn(f));
    lo = f - hi;
}

#define MMA_BF16(c, a, b0v, b1v) \
  asm volatile("mma.sync.aligned.m16n8k16.row.col.f32.bf16.bf16.f32 " \
    "{%0,%1,%2,%3}, {%4,%5,%6,%7}, {%8,%9}, {%0,%1,%2,%3};" \
    : "+f"((c)[0]), "+f"((c)[1]), "+f"((c)[2]), "+f"((c)[3]) \
    : "r"((a)[0]), "r"((a)[1]), "r"((a)[2]), "r"((a)[3]), "r"(b0v), "r"(b1v))

__device__ __forceinline__ void ldsm4(uint32_t* r, const uint32_t* p) {
    uint32_t a = (uint32_t)__cvta_generic_to_shared(p);
    asm volatile("ldmatrix.sync.aligned.m8n8.x4.shared.b16 {%0,%1,%2,%3}, [%4];"
        : "=r"(r[0]), "=r"(r[1]), "=r"(r[2]), "=r"(r[3]) : "r"(a));
}
__device__ __forceinline__ void ldsm4t(uint32_t* r, const uint32_t* p) {
    uint32_t a = (uint32_t)__cvta_generic_to_shared(p);
    asm volatile("ldmatrix.sync.aligned.m8n8.x4.trans.shared.b16 {%0,%1,%2,%3}, [%4];"
        : "=r"(r[0]), "=r"(r[1]), "=r"(r[2]), "=r"(r[3]) : "r"(a));
}
__device__ __forceinline__ void cpa(uint32_t* dst, const void* src) {
    uint32_t d = (uint32_t)__cvta_generic_to_shared(dst);
    asm volatile("cp.async.cg.shared.global [%0], [%1], 16;" :: "r"(d), "l"(src));
}
#define CP_COMMIT asm volatile("cp.async.commit_group;")

// ---------------- conversion fp32 -> bf16 hi/lo with section remap ----------------
// float4 index i -> layer l = i/layer4, rem r; dst4 = l*stride4 + off4 + r
__global__ void cvt_kernel(const float* __restrict__ s, bf16* __restrict__ dh,
                           bf16* __restrict__ dl, int total4, int layer4,
                           int stride4, int off4) {
    int i = blockIdx.x * blockDim.x + threadIdx.x;
    if (i >= total4) return;
    int l = i / layer4;
    int r = i - l * layer4;
    size_t dst = ((size_t)l * stride4 + off4 + r) * 2;
    float4 v = reinterpret_cast<const float4*>(s)[i];
    float h0,l0,h1,l1,h2,l2,h3,l3;
    split2(v.x,h0,l0); split2(v.y,h1,l1); split2(v.z,h2,l2); split2(v.w,h3,l3);
    reinterpret_cast<uint32_t*>(dh)[dst]   = pack2bf(h0,h1);
    reinterpret_cast<uint32_t*>(dh)[dst+1] = pack2bf(h2,h3);
    reinterpret_cast<uint32_t*>(dl)[dst]   = pack2bf(l0,l1);
    reinterpret_cast<uint32_t*>(dl)[dst+1] = pack2bf(l2,l3);
}

// pack qkv biases: [L,3,D]
__global__ void pack_bias_kernel(const float* __restrict__ bq, const float* __restrict__ bk,
                                 const float* __restrict__ bv, float* __restrict__ dst) {
    int t = blockIdx.x * blockDim.x + threadIdx.x;
    if (t >= LL * D3) return;
    int l = t / D3;
    int rem = t - l * D3;
    int sec = rem / DD, d = rem - sec * DD;
    const float* src = (sec == 0) ? bq : (sec == 1) ? bk : bv;
    dst[t] = src[l * DD + d];
}

// ---------------- embedding ----------------
__global__ void embed_kernel(const int* __restrict__ idx,
                             const float* __restrict__ tok,
                             const float* __restrict__ pos,
                             float* __restrict__ x) {
    int row = blockIdx.x;
    int t   = row & (TT - 1);
    int token = idx[row];
    const float4* tr = reinterpret_cast<const float4*>(tok + (size_t)token * DD);
    const float4* pr = reinterpret_cast<const float4*>(pos + (size_t)t * DD);
    float4* xr = reinterpret_cast<float4*>(x + (size_t)row * DD);
    int i = threadIdx.x;
    float4 a = tr[i], p = pr[i];
    float4 o; o.x = a.x + p.x; o.y = a.y + p.y; o.z = a.z + p.z; o.w = a.w + p.w;
    xr[i] = o;
}

// ---------------- layernorm -> bf16 hi/lo ----------------
__global__ void ln_kernel(const float* __restrict__ in, bf16* __restrict__ outh,
                          bf16* __restrict__ outl,
                          const float* __restrict__ w, const float* __restrict__ b) {
    __shared__ float red[8];
    __shared__ float s_mean, s_rstd;
    int row = blockIdx.x;
    int tid = threadIdx.x;
    int lane = tid & 31, wid = tid >> 5;

    const float4* r = reinterpret_cast<const float4*>(in + (size_t)row * DD);
    float4 v = r[tid];

    float s = v.x + v.y + v.z + v.w;
    s = warpSum(s);
    if (lane == 0) red[wid] = s;
    __syncthreads();
    if (wid == 0) {
        float t = (lane < 8) ? red[lane] : 0.f;
        t = warpSum(t);
        if (lane == 0) s_mean = t * (1.0f / DD);
    }
    __syncthreads();
    float mean = s_mean;
    float dx = v.x - mean, dy = v.y - mean, dz = v.z - mean, dw = v.w - mean;
    float sq = dx*dx + dy*dy + dz*dz + dw*dw;
    sq = warpSum(sq);
    __syncthreads();
    if (lane == 0) red[wid] = sq;
    __syncthreads();
    if (wid == 0) {
        float t = (lane < 8) ? red[lane] : 0.f;
        t = warpSum(t);
        if (lane == 0) s_rstd = rsqrtf(t * (1.0f / DD) + 1e-5f);
    }
    __syncthreads();
    float rstd = s_rstd;

    const float4* wr = reinterpret_cast<const float4*>(w);
    const float4* br = reinterpret_cast<const float4*>(b);
    float4 ww = wr[tid], bb = br[tid];
    float ox = dx * rstd * ww.x + bb.x;
    float oy = dy * rstd * ww.y + bb.y;
    float oz = dz * rstd * ww.z + bb.z;
    float ow = dw * rstd * ww.w + bb.w;
    float h0,l0,h1,l1,h2,l2,h3,l3;
    split2(ox,h0,l0); split2(oy,h1,l1); split2(oz,h2,l2); split2(ow,h3,l3);
    uint32_t* oh = reinterpret_cast<uint32_t*>(outh) + (size_t)row * 512;
    uint32_t* ol = reinterpret_cast<uint32_t*>(outl) + (size_t)row * 512;
    oh[tid*2]   = pack2bf(h0,h1);
    oh[tid*2+1] = pack2bf(h2,h3);
    ol[tid*2]   = pack2bf(l0,l1);
    ol[tid*2+1] = pack2bf(l2,l3);
}

// ---------------- bf16-split tensor-core GEMM, cp.async, 128x128, 256 thr ----------
// stage (u32): Ah[128][20] | Al | Bh | Bl = 10240 u32 = 40960 B; 2 stages.
__device__ __forceinline__ void gemm_issue(uint32_t* st,
        const bf16* __restrict__ Ah, const bf16* __restrict__ Al,
        const bf16* __restrict__ Wh, const bf16* __restrict__ Wl,
        size_t ko, int bm, int bn, int K, int arow, int ac) {
    const size_t aoff = (size_t)(bm + arow) * K + ko;
    const size_t boff = (size_t)(bn + arow) * K + ko;
    #pragma unroll
    for (int i = 0; i < 2; i++) {
        int c = ac + i;
        cpa(st + arow*20 + c*4,        Ah + aoff + c*8);
        cpa(st + 2560 + arow*20 + c*4, Al + aoff + c*8);
        cpa(st + 5120 + arow*20 + c*4, Wh + boff + c*8);
        cpa(st + 7680 + arow*20 + c*4, Wl + boff + c*8);
    }
}

template <int GELU, int RES, int OUTBF>
__global__ void __launch_bounds__(256, 2)
mma_gemm(const bf16* __restrict__ Ah, const bf16* __restrict__ Al,
         const bf16* __restrict__ Wh, const bf16* __restrict__ Wl,
         const float* __restrict__ bias, const float* __restrict__ res,
         float* __restrict__ C, float* __restrict__ C2,
         bf16* __restrict__ Ch, bf16* __restrict__ Cl,
         int M, int N, int K, int ldc, int nsplit) {
    extern __shared__ uint32_t sm[];

    const int t = threadIdx.x;
    const int lane = t & 31, wid = t >> 5;
    const int wm = (wid & 3) * 32;
    const int wn = (wid >> 2) * 64;
    const int gid = lane >> 2, tig = lane & 3;
    const int bm = blockIdx.y * 128;
    const int bn = blockIdx.x * 128;

    float acc[2][8][4];
    #pragma unroll
    for (int mt = 0; mt < 2; mt++)
        #pragma unroll
        for (int nt = 0; nt < 8; nt++)
            #pragma unroll
            for (int i = 0; i < 4; i++) acc[mt][nt][i] = 0.f;

    const int arow = t >> 1, ac = (t & 1) * 2;
    const int a_r = wm + (lane & 15);
    const int a_cofs = (lane >> 4) << 2;
    const int b_r = wn + (lane & 7) + ((lane & 16) ? 8 : 0);
    const int b_cofs = (lane & 8) ? 4 : 0;

    const int ktot = K >> 5;
    gemm_issue(sm, Ah, Al, Wh, Wl, 0, bm, bn, K, arow, ac);
    CP_COMMIT;

    for (int kt = 0; kt < ktot; kt++) {
        if (kt + 1 < ktot) {
            gemm_issue(sm + ((kt+1)&1)*10240, Ah, Al, Wh, Wl,
                       (size_t)(kt+1)*32, bm, bn, K, arow, ac);
            CP_COMMIT;
            asm volatile("cp.async.wait_group 1;");
        } else {
            asm volatile("cp.async.wait_group 0;");
        }
        __syncthreads();
        uint32_t* st = sm + (kt & 1) * 10240;

        #pragma unroll
        for (int ks = 0; ks < 2; ks++) {
            uint32_t ah[2][4], al[2][4];
            int acol = ks * 8 + a_cofs;
            ldsm4(ah[0], st + (size_t)a_r * 20 + acol);
            ldsm4(ah[1], st + (size_t)(a_r + 16) * 20 + acol);
            ldsm4(al[0], st + 2560 + (size_t)a_r * 20 + acol);
            ldsm4(al[1], st + 2560 + (size_t)(a_r + 16) * 20 + acol);
            #pragma unroll
            for (int ntp = 0; ntp < 4; ntp++) {
                int br2 = b_r + ntp * 16;
                int bcol = ks * 8 + b_cofs;
                uint32_t bh[4], bl[4];
                ldsm4(bh, st + 5120 + (size_t)br2 * 20 + bcol);
                ldsm4(bl, st + 7680 + (size_t)br2 * 20 + bcol);
                // interleave split terms across 4 independent accumulators
                #pragma unroll
                for (int half = 0; half < 2; half++)
                    #pragma unroll
                    for (int mt = 0; mt < 2; mt++)
                        MMA_BF16(acc[mt][ntp*2+half], ah[mt], bh[half*2], bh[half*2+1]);
                #pragma unroll
                for (int half = 0; half < 2; half++)
                    #pragma unroll
                    for (int mt = 0; mt < 2; mt++)
                        MMA_BF16(acc[mt][ntp*2+half], ah[mt], bl[half*2], bl[half*2+1]);
                #pragma unroll
                for (int half = 0; half < 2; half++)
                    #pragma unroll
                    for (int mt = 0; mt < 2; mt++)
                        MMA_BF16(acc[mt][ntp*2+half], al[mt], bh[half*2], bh[half*2+1]);
            }
        }
        __syncthreads();
    }

    // epilogue
    #pragma unroll
    for (int mt = 0; mt < 2; mt++) {
        int r0 = bm + wm + mt * 16 + gid;
        #pragma unroll
        for (int nt = 0; nt < 8; nt++) {
            int c = bn + wn + nt * 8 + tig * 2;
            float b0 = 0.f, b1 = 0.f;
            if (bias) { b0 = bias[c]; b1 = bias[c + 1]; }
            float v0 = acc[mt][nt][0] + b0, v1 = acc[mt][nt][1] + b1;
            float v2 = acc[mt][nt][2] + b0, v3 = acc[mt][nt][3] + b1;
            if (RES) {
                float2 ra = *reinterpret_cast<const float2*>(&res[(size_t)r0 * ldc + c]);
                float2 rb = *reinterpret_cast<const float2*>(&res[(size_t)(r0 + 8) * ldc + c]);
                v0 += ra.x; v1 += ra.y; v2 += rb.x; v3 += rb.y;
            }
            if (GELU) {
                v0 = 0.5f * v0 * (1.0f + erff(v0 * 0.70710678118654752f));
                v1 = 0.5f * v1 * (1.0f + erff(v1 * 0.70710678118654752f));
                v2 = 0.5f * v2 * (1.0f + erff(v2 * 0.70710678118654752f));
                v3 = 0.5f * v3 * (1.0f + erff(v3 * 0.70710678118654752f));
            }
            if (OUTBF) {
                float h0,l0,h1,l1;
                split2(v0,h0,l0); split2(v1,h1,l1);
                *reinterpret_cast<uint32_t*>(Ch + (size_t)r0 * ldc + c) = pack2bf(h0,h1);
                *reinterpret_cast<uint32_t*>(Cl + (size_t)r0 * ldc + c) = pack2bf(l0,l1);
                split2(v2,h0,l0); split2(v3,h1,l1);
                *reinterpret_cast<uint32_t*>(Ch + (size_t)(r0+8) * ldc + c) = pack2bf(h0,h1);
                *reinterpret_cast<uint32_t*>(Cl + (size_t)(r0+8) * ldc + c) = pack2bf(l0,l1);
            } else {
                float* Co = C;
                int cc = c;
                if (cc >= nsplit) { Co = C2; cc -= nsplit; }
                *reinterpret_cast<float2*>(&Co[(size_t)r0 * ldc + cc])       = make_float2(v0, v1);
                *reinterpret_cast<float2*>(&Co[(size_t)(r0 + 8) * ldc + cc]) = make_float2(v2, v3);
            }
        }
    }
}

// ---------------- tensorized flash attention (fused qkv input) ----------------
// block: 64 q x (h,b), 128 threads (4 warps x 16q). K/V tiles of 32.
__global__ void __launch_bounds__(128)
attn_kernel(const bf16* __restrict__ qkvh, const bf16* __restrict__ qkvl,
            bf16* __restrict__ gyh, bf16* __restrict__ gyl) {
    __shared__ uint32_t Qh[64*36], Ql[64*36];
    __shared__ uint32_t Kh[32*36], Kl[32*36];
    __shared__ uint32_t Vh[32*36], Vl[32*36];

    const int q0 = blockIdx.x * 64;
    const int h  = blockIdx.y;
    const int b  = blockIdx.z;
    const int tid = threadIdx.x;
    const int lane = tid & 31, wid = tid >> 5;
    const int gid = lane >> 2, tig = lane & 3;
    const int wq = wid * 16;
    const size_t base  = ((size_t)b * TT) * D3 + h * HD;   // q section
    const size_t ybase = ((size_t)b * TT) * DD + h * HD;

    // stage Q tile (64 x 64 bf16, hi+lo)
    #pragma unroll
    for (int i = 0; i < 4; i++) {
        int chunk = tid + i * 128;
        int row = chunk >> 3, c = chunk & 7;
        const size_t g = base + (size_t)(q0 + row) * D3 + c * 8;
        *reinterpret_cast<uint4*>(Qh + row*36 + c*4) = *reinterpret_cast<const uint4*>(qkvh + g);
        *reinterpret_cast<uint4*>(Ql + row*36 + c*4) = *reinterpret_cast<const uint4*>(qkvl + g);
    }

    float m0 = -1e30f, m1 = -1e30f, l0s = 0.f, l1s = 0.f;
    float acc[8][4];
    #pragma unroll
    for (int i = 0; i < 8; i++)
        #pragma unroll
        for (int j = 0; j < 4; j++) acc[i][j] = 0.f;

    const int qg0 = q0 + wq + gid;
    const int qmax = q0 + wq + 15;
    const int ntiles = (q0 + 64) >> 5;

    const int a_r = wq + (lane & 15);
    const int a_cofs = (lane >> 4) << 2;
    const int b_r = (lane & 7) + ((lane & 16) ? 8 : 0);
    const int b_cofs = (lane & 8) ? 4 : 0;
    const int v_r = (lane & 7) + ((lane & 8) ? 8 : 0);
    const int v_cofs = (lane & 16) ? 4 : 0;

    for (int kt = 0; kt < ntiles; kt++) {
        int k0 = kt * 32;
        __syncthreads();
        #pragma unroll
        for (int i = 0; i < 2; i++) {
            int chunk = tid + i * 128;
            int row = chunk >> 3, c = chunk & 7;
            const size_t g = base + (size_t)(k0 + row) * D3 + c * 8;
            *reinterpret_cast<uint4*>(Kh + row*36 + c*4) = *reinterpret_cast<const uint4*>(qkvh + g + DD);
            *reinterpret_cast<uint4*>(Kl + row*36 + c*4) = *reinterpret_cast<const uint4*>(qkvl + g + DD);
            *reinterpret_cast<uint4*>(Vh + row*36 + c*4) = *reinterpret_cast<const uint4*>(qkvh + g + 2*DD);
            *reinterpret_cast<uint4*>(Vl + row*36 + c*4) = *reinterpret_cast<const uint4*>(qkvl + g + 2*DD);
        }
        __syncthreads();
        if (k0 > qmax) continue;

        // ---- scores ----
        float s[4][4];
        #pragma unroll
        for (int nt = 0; nt < 4; nt++)
            #pragma unroll
            for (int j = 0; j < 4; j++) s[nt][j] = 0.f;

        #pragma unroll
        for (int ks = 0; ks < 4; ks++) {
            uint32_t ah[4], al[4];
            int acol = ks * 8 + a_cofs;
            ldsm4(ah, Qh + (size_t)a_r * 36 + acol);
            ldsm4(al, Ql + (size_t)a_r * 36 + acol);
            #pragma unroll
            for (int ntp = 0; ntp < 2; ntp++) {
                int brow = b_r + ntp * 16;
                int bcol = ks * 8 + b_cofs;
                uint32_t bh[4], bl[4];
                ldsm4(bh, Kh + (size_t)brow * 36 + bcol);
                ldsm4(bl, Kl + (size_t)brow * 36 + bcol);
                #pragma unroll
                for (int half = 0; half < 2; half++) {
                    int nt = ntp * 2 + half;
                    MMA_BF16(s[nt], ah, bh[half*2], bh[half*2+1]);
                    MMA_BF16(s[nt], ah, bl[half*2], bl[half*2+1]);
                    MMA_BF16(s[nt], al, bh[half*2], bh[half*2+1]);
                }
            }
        }

        // scale + causal mask
        #pragma unroll
        for (int nt = 0; nt < 4; nt++)
            #pragma unroll
            for (int j = 0; j < 4; j++) s[nt][j] *= 0.125f;
        if (k0 + 31 > q0 + wq) {
            #pragma unroll
            for (int nt = 0; nt < 4; nt++) {
                int kg = k0 + nt * 8 + tig * 2;
                if (kg     > qg0)     s[nt][0] = -1e30f;
                if (kg + 1 > qg0)     s[nt][1] = -1e30f;
                if (kg     > qg0 + 8) s[nt][2] = -1e30f;
                if (kg + 1 > qg0 + 8) s[nt][3] = -1e30f;
            }
        }

        // online softmax
        float mx0 = -1e30f, mx1 = -1e30f;
        #pragma unroll
        for (int nt = 0; nt < 4; nt++) {
            mx0 = fmaxf(mx0, fmaxf(s[nt][0], s[nt][1]));
            mx1 = fmaxf(mx1, fmaxf(s[nt][2], s[nt][3]));
        }
        mx0 = fmaxf(mx0, __shfl_xor_sync(0xffffffffu, mx0, 1));
        mx0 = fmaxf(mx0, __shfl_xor_sync(0xffffffffu, mx0, 2));
        mx1 = fmaxf(mx1, __shfl_xor_sync(0xffffffffu, mx1, 1));
        mx1 = fmaxf(mx1, __shfl_xor_sync(0xffffffffu, mx1, 2));
        float mn0 = fmaxf(m0, mx0), mn1 = fmaxf(m1, mx1);
        float sc0 = __expf(m0 - mn0), sc1 = __expf(m1 - mn1);
        m0 = mn0; m1 = mn1;
        float rs0 = 0.f, rs1 = 0.f;
        #pragma unroll
        for (int nt = 0; nt < 4; nt++) {
            s[nt][0] = __expf(s[nt][0] - mn0);
            s[nt][1] = __expf(s[nt][1] - mn0);
            s[nt][2] = __expf(s[nt][2] - mn1);
            s[nt][3] = __expf(s[nt][3] - mn1);
            rs0 += s[nt][0] + s[nt][1];
            rs1 += s[nt][2] + s[nt][3];
        }
        rs0 += __shfl_xor_sync(0xffffffffu, rs0, 1);
        rs0 += __shfl_xor_sync(0xffffffffu, rs0, 2);
        rs1 += __shfl_xor_sync(0xffffffffu, rs1, 1);
        rs1 += __shfl_xor_sync(0xffffffffu, rs1, 2);
        l0s = l0s * sc0 + rs0;
        l1s = l1s * sc1 + rs1;
        #pragma unroll
        for (int ntd = 0; ntd < 8; ntd++) {
            acc[ntd][0] *= sc0; acc[ntd][1] *= sc0;
            acc[ntd][2] *= sc1; acc[ntd][3] *= sc1;
        }

        // ---- PV ----
        #pragma unroll
        for (int ks2 = 0; ks2 < 2; ks2++) {
            int e = ks2 * 2, o = e + 1;
            uint32_t ph[4], pl[4];
            {
                float h0,L0,h1,L1;
                split2(s[e][0],h0,L0); split2(s[e][1],h1,L1);
                ph[0] = pack2bf(h0,h1); pl[0] = pack2bf(L0,L1);
                split2(s[e][2],h0,L0); split2(s[e][3],h1,L1);
                ph[1] = pack2bf(h0,h1); pl[1] = pack2bf(L0,L1);
                split2(s[o][0],h0,L0); split2(s[o][1],h1,L1);
                ph[2] = pack2bf(h0,h1); pl[2] = pack2bf(L0,L1);
                split2(s[o][2],h0,L0); split2(s[o][3],h1,L1);
                ph[3] = pack2bf(h0,h1); pl[3] = pack2bf(L0,L1);
            }
            #pragma unroll
            for (int ntp = 0; ntp < 4; ntp++) {
                int vrow = ks2 * 16 + v_r;
                int vcol = ntp * 8 + v_cofs;
                uint32_t bh[4], bl[4];
                ldsm4t(bh, Vh + (size_t)vrow * 36 + vcol);
                ldsm4t(bl, Vl + (size_t)vrow * 36 + vcol);
                #pragma unroll
                for (int half = 0; half < 2; half++) {
                    int ntd = ntp * 2 + half;
                    MMA_BF16(acc[ntd], ph, bh[half*2], bh[half*2+1]);
                    MMA_BF16(acc[ntd], ph, bl[half*2], bl[half*2+1]);
                    MMA_BF16(acc[ntd], pl, bh[half*2], bh[half*2+1]);
                }
            }
        }
    }

    // write out (bf16 hi/lo)
    float inv0 = 1.0f / l0s, inv1 = 1.0f / l1s;
    #pragma unroll
    for (int ntd = 0; ntd < 8; ntd++) {
        int d = ntd * 8 + tig * 2;
        float h0,L0,h1,L1;
        split2(acc[ntd][0] * inv0, h0, L0); split2(acc[ntd][1] * inv0, h1, L1);
        *reinterpret_cast<uint32_t*>(gyh + ybase + (size_t)qg0 * DD + d) = pack2bf(h0,h1);
        *reinterpret_cast<uint32_t*>(gyl + ybase + (size_t)qg0 * DD + d) = pack2bf(L0,L1);
        split2(acc[ntd][2] * inv1, h0, L0); split2(acc[ntd][3] * inv1, h1, L1);
        *reinterpret_cast<uint32_t*>(gyh + ybase + (size_t)(qg0 + 8) * DD + d) = pack2bf(h0,h1);
        *reinterpret_cast<uint32_t*>(gyl + ybase + (size_t)(qg0 + 8) * DD + d) = pack2bf(L0,L1);
    }
}

// ---------------- launch ----------------
extern "C" void kernel_launch(void* const* d_in, const int* in_sizes, int n_in,
                              void* d_out, int out_size) {
    const int*   idx    = (const int*)  d_in[0];
    const float* tok    = (const float*)d_in[1];
    const float* pos    = (const float*)d_in[2];
    const float* ln1_w  = (const float*)d_in[3];
    const float* ln1_b  = (const float*)d_in[4];
    const float* Wq     = (const float*)d_in[5];
    const float* bq     = (const float*)d_in[6];
    const float* Wk     = (const float*)d_in[7];
    const float* bk     = (const float*)d_in[8];
    const float* Wv     = (const float*)d_in[9];
    const float* bv     = (const float*)d_in[10];
    const float* Wproj  = (const float*)d_in[11];
    const float* bproj  = (const float*)d_in[12];
    const float* ln2_w  = (const float*)d_in[13];
    const float* ln2_b  = (const float*)d_in[14];
    const float* W1     = (const float*)d_in[15];
    const float* b1     = (const float*)d_in[16];
    const float* W2     = (const float*)d_in[17];
    const float* b2     = (const float*)d_in[18];
    const float* lnf_w  = (const float*)d_in[19];
    const float* lnf_b  = (const float*)d_in[20];
    const float* Wlogit = (const float*)d_in[21];
    const float* Wdev   = (const float*)d_in[22];
    float* out = (float*)d_out;

    float *x, *bqkv;
    bf16 *hh,*hl,*qkvh,*qkvl,*yh,*yl,*mh,*ml;
    bf16 *wqkvh,*wqkvl,*wph,*wpl,*w1h,*w1l,*w2h,*w2l,*whh,*whl;
    cudaGetSymbolAddress((void**)&x,     g_x);
    cudaGetSymbolAddress((void**)&bqkv,  g_bqkv);
    cudaGetSymbolAddress((void**)&hh,    g_hh);    cudaGetSymbolAddress((void**)&hl,    g_hl);
    cudaGetSymbolAddress((void**)&qkvh,  g_qkvh);  cudaGetSymbolAddress((void**)&qkvl,  g_qkvl);
    cudaGetSymbolAddress((void**)&yh,    g_yh);    cudaGetSymbolAddress((void**)&yl,    g_yl);
    cudaGetSymbolAddress((void**)&mh,    g_mh);    cudaGetSymbolAddress((void**)&ml,    g_ml);
    cudaGetSymbolAddress((void**)&wqkvh, g_wqkvh); cudaGetSymbolAddress((void**)&wqkvl, g_wqkvl);
    cudaGetSymbolAddress((void**)&wph,   g_wph);   cudaGetSymbolAddress((void**)&wpl,   g_wpl);
    cudaGetSymbolAddress((void**)&w1h,   g_w1h);   cudaGetSymbolAddress((void**)&w1l,   g_w1l);
    cudaGetSymbolAddress((void**)&w2h,   g_w2h);   cudaGetSymbolAddress((void**)&w2l,   g_w2l);
    cudaGetSymbolAddress((void**)&whh,   g_whh);   cudaGetSymbolAddress((void**)&whl,   g_whl);

    const int SMEM = 2 * 10240 * 4;   // 81920
    cudaFuncSetAttribute(mma_gemm<0,0,1>, cudaFuncAttributeMaxDynamicSharedMemorySize, SMEM);
    cudaFuncSetAttribute(mma_gemm<0,1,0>, cudaFuncAttributeMaxDynamicSharedMemorySize, SMEM);
    cudaFuncSetAttribute(mma_gemm<1,0,1>, cudaFuncAttributeMaxDynamicSharedMemorySize, SMEM);
    cudaFuncSetAttribute(mma_gemm<0,0,0>, cudaFuncAttributeMaxDynamicSharedMemorySize, SMEM);

    // weight conversion + packing
    {
        const int LAY = DD*DD/4;             // 262144 float4 / layer
        int n4q = LL*LAY;                     // per-matrix qkv
        int n41 = (int)((size_t)LL*D4*DD/4);  // 8M
        int n4v = VV*DD/4;                    // 1M
        cvt_kernel<<<(n4q+255)/256, 256>>>(Wq, wqkvh, wqkvl, n4q, LAY, 3*LAY, 0);
        cvt_kernel<<<(n4q+255)/256, 256>>>(Wk, wqkvh, wqkvl, n4q, LAY, 3*LAY, LAY);
        cvt_kernel<<<(n4q+255)/256, 256>>>(Wv, wqkvh, wqkvl, n4q, LAY, 3*LAY, 2*LAY);
        cvt_kernel<<<(n4q+255)/256, 256>>>(Wproj, wph, wpl, n4q, n4q, n4q, 0);
        cvt_kernel<<<(n41+255)/256, 256>>>(W1, w1h, w1l, n41, n41, n41, 0);
        cvt_kernel<<<(n41+255)/256, 256>>>(W2, w2h, w2l, n41, n41, n41, 0);
        cvt_kernel<<<(n4v+255)/256, 256>>>(Wlogit, whh, whl, n4v, n4v, n4v, 0);
        // FIX: Wdev section starts at bf16 element VV*DD (was VV*DD/2 -> corrupted logit weights)
        cvt_kernel<<<(n4v+255)/256, 256>>>(Wdev, whh + (size_t)VV*DD, whl + (size_t)VV*DD,
                                           n4v, n4v, n4v, 0);
        pack_bias_kernel<<<(LL*D3+255)/256, 256>>>(bq, bk, bv, bqkv);
    }

    embed_kernel<<<BT, 256>>>(idx, tok, pos, x);

    dim3 gQKV(D3 / 128, BT / 128);   // (24,32)
    dim3 gD(DD / 128, BT / 128);     // (8,32)
    dim3 g4(D4 / 128, BT / 128);     // (32,32)
    dim3 gH(2*VV / 128, BT / 128);   // (64,32)
    dim3 ga(TT / 64, HH, BB);
    const int BIG = 1 << 30;

    for (int l = 0; l < LL; l++) {
        size_t woq = (size_t)l * D3 * DD;
        size_t wo  = (size_t)l * DD * DD;
        size_t w4  = (size_t)l * D4 * DD;

        ln_kernel<<<BT, 256>>>(x, hh, hl, ln1_w + l * DD, ln1_b + l * DD);

        mma_gemm<0,0,1><<<gQKV, 256, SMEM>>>(hh, hl, wqkvh + woq, wqkvl + woq,
            bqkv + l * D3, nullptr, nullptr, nullptr, qkvh, qkvl, BT, D3, DD, D3, BIG);

        attn_kernel<<<ga, 128>>>(qkvh, qkvl, yh, yl);

        mma_gemm<0,1,0><<<gD, 256, SMEM>>>(yh, yl, wph + wo, wpl + wo, bproj + l * DD,
            x, x, nullptr, nullptr, nullptr, BT, DD, DD, DD, BIG);

        ln_kernel<<<BT, 256>>>(x, hh, hl, ln2_w + l * DD, ln2_b + l * DD);

        mma_gemm<1,0,1><<<g4, 256, SMEM>>>(hh, hl, w1h + w4, w1l + w4, b1 + (size_t)l * D4,
            nullptr, nullptr, nullptr, mh, ml, BT, D4, DD, D4, BIG);

        mma_gemm<0,1,0><<<gD, 256, SMEM>>>(mh, ml, w2h + w4, w2l + w4, b2 + l * DD,
            x, x, nullptr, nullptr, nullptr, BT, DD, D4, DD, BIG);
    }

    ln_kernel<<<BT, 256>>>(x, hh, hl, lnf_w, lnf_b);

    // fused heads: N=8192, split at 4096 into logits / dev halves of d_out
    mma_gemm<0,0,0><<<gH, 256, SMEM>>>(hh, hl, whh, whl, nullptr, nullptr,
        out, out + (size_t)BT * VV, nullptr, nullptr, BT, 2*VV, DD, VV, VV);
}